// round 15
// baseline (speedup 1.0000x reference)
#include <cuda_runtime.h>
#include <cuda_fp16.h>

// ---------------------------------------------------------------------------
// GNNBlock via warp-level mma.sync fp16 (fp32 accumulate), sm_103-safe ISA.
// R14: REGISTER-RESIDENT P. Softmax is computed per-warp directly in the
//      m16n8k16 A-fragment layout (factorized exp tables, no MUFU), scaled
//      with mul.f16x2, and fed straight to the aggregation MMAs: no P smem
//      buffer traffic and zero barriers inside the heads loop.
// GEMM = R9 staged version (fp16 pre-converted W, 2-dbuf, 1 sync/chunk).
// 512 threads/CTA, 2 CTAs/SM. H row-major [node][ch], agg B via ldsm.trans.
// ---------------------------------------------------------------------------

typedef unsigned int uint_t;
typedef unsigned long long ull_t;

// ------------------------- smem byte offsets (per CTA: 109824 B) -----------
#define OFF_P0   0          // X / X2 buffer: 128 rows x 136 fp16 (272 B)
#define OFF_H    34816      // H: 128 rows x 200 fp16 (400 B stride)
#define OFF_BST  86016      // W staging: 2 dbuf x 6400 B
#define OFF_SS   98816      // src scores 3x128 f32
#define OFF_SD   100352     // dst scores 3x128 f32
#define OFF_ES   101888     // exp(S) 3x128 f32
#define OFF_ES2  103424     // exp(0.2 S)
#define OFF_ED   104960     // exp(D)
#define OFF_ED2  106496     // exp(0.2 D)
#define OFF_ATT  108032     // att vecs 2x192 f32
#define OFF_SF   109568     // final pool 64 f32
#define SMEM_BYTES 109824

#define HSTRIDE_B 400       // H / staging row stride bytes
#define STG_DBUF  6400      // staging dbuf stride

// fp16 weight scratch (filled once per launch by cvt_weights)
__device__ __half g_W1h[128 * 192];
__device__ __half g_W2h[64 * 192];

__global__ void cvt_weights(const float* __restrict__ W1,
                            const float* __restrict__ W2) {
    const int i = blockIdx.x * 256 + threadIdx.x;
    if (i < 128 * 192) g_W1h[i] = __float2half(W1[i]);
    if (i < 64 * 192)  g_W2h[i] = __float2half(W2[i]);
}

__device__ __forceinline__ uint_t smem_u32(const void* p) {
    uint_t a;
    asm("{ .reg .u64 t; cvta.to.shared.u64 t, %1; cvt.u32.u64 %0, t; }"
        : "=r"(a) : "l"(p));
    return a;
}
__device__ __forceinline__ void ldsm4(uint_t r[4], uint_t addr) {
    asm volatile("ldmatrix.sync.aligned.m8n8.x4.shared.b16 {%0,%1,%2,%3}, [%4];"
        : "=r"(r[0]), "=r"(r[1]), "=r"(r[2]), "=r"(r[3]) : "r"(addr));
}
__device__ __forceinline__ void ldsm4t(uint_t r[4], uint_t addr) {
    asm volatile("ldmatrix.sync.aligned.m8n8.x4.trans.shared.b16 {%0,%1,%2,%3}, [%4];"
        : "=r"(r[0]), "=r"(r[1]), "=r"(r[2]), "=r"(r[3]) : "r"(addr));
}
__device__ __forceinline__ void mma16816(float d[4], const uint_t a[4],
                                         uint_t b0, uint_t b1) {
    asm volatile("mma.sync.aligned.m16n8k16.row.col.f32.f16.f16.f32 "
        "{%0,%1,%2,%3}, {%4,%5,%6,%7}, {%8,%9}, {%0,%1,%2,%3};"
        : "+f"(d[0]), "+f"(d[1]), "+f"(d[2]), "+f"(d[3])
        : "r"(a[0]), "r"(a[1]), "r"(a[2]), "r"(a[3]), "r"(b0), "r"(b1));
}
// pack (lo, hi) in memory order as fp16x2
__device__ __forceinline__ uint_t pk2(float lo, float hi) {
    uint_t r;
    asm("cvt.rn.f16x2.f32 %0, %1, %2;" : "=r"(r) : "f"(hi), "f"(lo));
    return r;
}
__device__ __forceinline__ uint_t hmul2(uint_t a, uint_t b) {
    uint_t r;
    asm("mul.rn.f16x2 %0, %1, %2;" : "=r"(r) : "r"(a), "r"(b));
    return r;
}

// ---------------------------------------------------------------------------
// GEMM: H (row-major fp16) <- A[128 x 16*NCH] @ W[16*NCH x 192] (W fp16),
// fused per-node attention score partials via smem atomics.
// 16 warps: m0=(w&7)*16, n0=(w>>3)*96 -> 12 m16n8 tiles per warp.
// W staged [k][192] fp16 (2 dbuf, 1 sync/chunk), B fragments via ldsm.trans.
// ---------------------------------------------------------------------------
template <int NCH>
__device__ __forceinline__ void gemm_layer(const __half* __restrict__ Wg,
                                           char* smc, uint_t sbase, int tid) {
    const int warp = tid >> 5, lane = tid & 31;
    const int m0 = (warp & 7) * 16;
    const int n0 = (warp >> 3) * 96;

    float d[12][4];
#pragma unroll
    for (int p = 0; p < 12; p++)
#pragma unroll
        for (int q = 0; q < 4; q++) d[p][q] = 0.f;

    const uint_t aA = sbase + OFF_P0 + (m0 + (lane & 15)) * 272 + ((lane >> 4) << 4);
    const uint_t bOff = (lane & 15) * HSTRIDE_B + ((n0 + ((lane >> 4) << 3)) << 1);

    // staging producers: 768 x 8B per chunk; thread does idx=tid and
    // (tid<256) idx=tid+512.  sk=idx/48 (k row), sc=(idx%48)*4 (col).
    const int sk0 = tid / 48,         sc0 = (tid % 48) * 4;
    const int sk1 = (tid + 512) / 48, sc1 = ((tid + 512) % 48) * 4;
    ull_t pre0 = *(const ull_t*)(Wg + sk0 * 192 + sc0);
    ull_t pre1 = 0;
    if (tid < 256) pre1 = *(const ull_t*)(Wg + sk1 * 192 + sc1);

    for (int ch = 0; ch < NCH; ch++) {
        {
            char* stg = smc + OFF_BST + (ch & 1) * STG_DBUF;
            *(ull_t*)(stg + sk0 * HSTRIDE_B + sc0 * 2) = pre0;
            if (tid < 256)
                *(ull_t*)(stg + sk1 * HSTRIDE_B + sc1 * 2) = pre1;
        }
        __syncthreads();
        if (ch + 1 < NCH) {
            const __half* w = Wg + (ch + 1) * 16 * 192;
            pre0 = *(const ull_t*)(w + sk0 * 192 + sc0);
            if (tid < 256) pre1 = *(const ull_t*)(w + sk1 * 192 + sc1);
        }
        uint_t a[4];
        ldsm4(a, aA + ch * 32);
        const uint_t bB = sbase + OFF_BST + (ch & 1) * STG_DBUF + bOff;
#pragma unroll
        for (int pp = 0; pp < 6; pp++) {
            uint_t b[4];
            ldsm4t(b, bB + pp * 32);
            mma16816(d[2 * pp],     a, b[0], b[1]);
            mma16816(d[2 * pp + 1], a, b[2], b[3]);
        }
    }

    // ---- epilogue: H row-major STS.32 + fused score partials ----
    const int g = lane >> 2, tg = lane & 3;
    const float* sAtt = (const float*)(smc + OFF_ATT);
    float* sS = (float*)(smc + OFF_SS);
    float* sD = (float*)(smc + OFF_SD);
    const int first = n0 >> 6;        // 0 or 1; 96-col span covers 2 head slots
    const int r = m0 + g;

    float ps[2][2] = {{0.f, 0.f}, {0.f, 0.f}};
    float pd[2][2] = {{0.f, 0.f}, {0.f, 0.f}};
#pragma unroll
    for (int p = 0; p < 12; p++) {
        const int c = n0 + 8 * p + 2 * tg;
        const int slot = ((n0 + 8 * p) >> 6) - first;   // 0 or 1
        const float as0 = sAtt[c],       as1 = sAtt[c + 1];
        const float ad0 = sAtt[192 + c], ad1 = sAtt[192 + c + 1];
        const float q0 = d[p][0], q1 = d[p][1], q2 = d[p][2], q3 = d[p][3];
        char* base = smc + OFF_H + r * HSTRIDE_B + c * 2;
        *(uint_t*)(base)                 = pk2(q0, q1);
        *(uint_t*)(base + 8 * HSTRIDE_B) = pk2(q2, q3);
        ps[0][slot] += q0 * as0 + q1 * as1;
        pd[0][slot] += q0 * ad0 + q1 * ad1;
        ps[1][slot] += q2 * as0 + q3 * as1;
        pd[1][slot] += q2 * ad0 + q3 * ad1;
    }
#pragma unroll
    for (int rh = 0; rh < 2; rh++)
#pragma unroll
        for (int sl = 0; sl < 2; sl++) {
            float a = ps[rh][sl], b = pd[rh][sl];
            a += __shfl_xor_sync(0xffffffffu, a, 1);
            a += __shfl_xor_sync(0xffffffffu, a, 2);
            b += __shfl_xor_sync(0xffffffffu, b, 1);
            b += __shfl_xor_sync(0xffffffffu, b, 2);
            ps[rh][sl] = a; pd[rh][sl] = b;
        }
    if (tg == 0) {
#pragma unroll
        for (int rh = 0; rh < 2; rh++) {
            const int row = r + 8 * rh;
            atomicAdd(&sS[first * 128 + row],       ps[rh][0]);
            atomicAdd(&sD[first * 128 + row],       pd[rh][0]);
            atomicAdd(&sS[(first + 1) * 128 + row], ps[rh][1]);
            atomicAdd(&sD[(first + 1) * 128 + row], pd[rh][1]);
        }
    }
}

// ---------------------------------------------------------------------------
// Exp tables: thread t<384 handles (n, h): Es=e^S, Es2=e^{0.2S}, Ed, Ed2.
// The only MUFU work in the whole attention phase.
// ---------------------------------------------------------------------------
__device__ __forceinline__ void build_exp_tables(char* smc, int tid) {
    if (tid < 384) {
        const float s = ((const float*)(smc + OFF_SS))[tid];
        const float d = ((const float*)(smc + OFF_SD))[tid];
        ((float*)(smc + OFF_ES))[tid]  = __expf(s);
        ((float*)(smc + OFF_ES2))[tid] = __expf(0.2f * s);
        ((float*)(smc + OFF_ED))[tid]  = __expf(d);
        ((float*)(smc + OFF_ED2))[tid] = __expf(0.2f * d);
    }
}

// ---------------------------------------------------------------------------
// Fused softmax + aggregation, P register-resident in A-fragment layout.
// Warp w: m0=(w&7)*16 rows, n0=(w>>3)*32 cols of the output; for each head:
//   - compute its 16 rows' softmax weights directly as fragments
//     (thread owns rows {q, q+8}, cols {2t,2t+1,2t+8,2t+9} per 16-chunk)
//   - 2-shfl row-sum over the 4 lanes sharing a row, scale via mul.f16x2
//   - 32 MMAs against H_h (ldsm.trans B).  NO barriers, NO P smem traffic.
// ---------------------------------------------------------------------------
__device__ __forceinline__ void softmax_agg(float dA[4][4], char* smc,
                                            uint_t sbase, int tid) {
    const int warp = tid >> 5, lane = tid & 31;
    const int m0 = (warp & 7) * 16;
    const int n0 = (warp >> 3) * 32;
    const int q = lane >> 2, t = lane & 3;
    const int r0 = m0 + q, r1 = r0 + 8;
    const uint_t bBase = sbase + OFF_H + (lane & 15) * HSTRIDE_B
                       + ((n0 + ((lane >> 4) << 3)) << 1);

#pragma unroll 1
    for (int h = 0; h < 3; h++) {
        const float* Ss  = (const float*)(smc + OFF_SS)  + h * 128;
        const float* Es  = (const float*)(smc + OFF_ES)  + h * 128;
        const float* Es2 = (const float*)(smc + OFF_ES2) + h * 128;
        const float* Sd  = (const float*)(smc + OFF_SD)  + h * 128;
        const float* Ed  = (const float*)(smc + OFF_ED)  + h * 128;
        const float* Ed2 = (const float*)(smc + OFF_ED2) + h * 128;
        const float d0 = Sd[r0], d1 = Sd[r1];
        const float ed0 = Ed[r0], eb0 = Ed2[r0];
        const float ed1 = Ed[r1], eb1 = Ed2[r1];

        uint_t fr[8][4];
        float sum0 = 0.f, sum1 = 0.f;
#pragma unroll
        for (int ch = 0; ch < 8; ch++) {
            const int j0 = ch * 16 + 2 * t;
            const float2 sA = *(const float2*)(Ss + j0);
            const float2 sB = *(const float2*)(Ss + j0 + 8);
            const float2 eA = *(const float2*)(Es + j0);
            const float2 eB = *(const float2*)(Es + j0 + 8);
            const float2 qA = *(const float2*)(Es2 + j0);
            const float2 qB = *(const float2*)(Es2 + j0 + 8);
            const float e00 = (sA.x + d0 >= 0.f) ? eA.x * ed0 : qA.x * eb0;
            const float e01 = (sA.y + d0 >= 0.f) ? eA.y * ed0 : qA.y * eb0;
            const float e02 = (sB.x + d0 >= 0.f) ? eB.x * ed0 : qB.x * eb0;
            const float e03 = (sB.y + d0 >= 0.f) ? eB.y * ed0 : qB.y * eb0;
            const float e10 = (sA.x + d1 >= 0.f) ? eA.x * ed1 : qA.x * eb1;
            const float e11 = (sA.y + d1 >= 0.f) ? eA.y * ed1 : qA.y * eb1;
            const float e12 = (sB.x + d1 >= 0.f) ? eB.x * ed1 : qB.x * eb1;
            const float e13 = (sB.y + d1 >= 0.f) ? eB.y * ed1 : qB.y * eb1;
            sum0 += (e00 + e01) + (e02 + e03);
            sum1 += (e10 + e11) + (e12 + e13);
            fr[ch][0] = pk2(e00, e01);
            fr[ch][1] = pk2(e10, e11);
            fr[ch][2] = pk2(e02, e03);
            fr[ch][3] = pk2(e12, e13);
        }
        // row sums: 4 lanes (4q..4q+3) share each row
        sum0 += __shfl_xor_sync(0xffffffffu, sum0, 1);
        sum0 += __shfl_xor_sync(0xffffffffu, sum0, 2);
        sum1 += __shfl_xor_sync(0xffffffffu, sum1, 1);
        sum1 += __shfl_xor_sync(0xffffffffu, sum1, 2);
        const float i0 = __fdividef(1.f, sum0);
        const float i1 = __fdividef(1.f, sum1);
        const uint_t iv0 = pk2(i0, i0), iv1 = pk2(i1, i1);
#pragma unroll
        for (int ch = 0; ch < 8; ch++) {
            fr[ch][0] = hmul2(fr[ch][0], iv0);
            fr[ch][1] = hmul2(fr[ch][1], iv1);
            fr[ch][2] = hmul2(fr[ch][2], iv0);
            fr[ch][3] = hmul2(fr[ch][3], iv1);
        }
        // aggregate: dA += P_frag @ H_h
        const uint_t bB = bBase + (h << 7);     // +64h fp16 cols
#pragma unroll
        for (int s = 0; s < 8; s++) {
#pragma unroll
            for (int pp = 0; pp < 2; pp++) {
                uint_t b[4];
                ldsm4t(b, bB + s * (16 * HSTRIDE_B) + pp * 32);
                mma16816(dA[2 * pp],     fr[s], b[0], b[1]);
                mma16816(dA[2 * pp + 1], fr[s], b[2], b[3]);
            }
        }
    }
}

// ---------------------------------------------------------------------------
__global__ void __launch_bounds__(512, 2)
gat_mma_kernel(const float* __restrict__ x,
               const float* __restrict__ as1, const float* __restrict__ ad1,
               const float* __restrict__ b1,
               const float* __restrict__ as2, const float* __restrict__ ad2,
               const float* __restrict__ b2,
               float* __restrict__ out) {
    extern __shared__ char smc[];
    const uint_t sbase = smem_u32(smc);
    const int tid = threadIdx.x;
    const int warp = tid >> 5, lane = tid & 31;

    float* sAtt = (float*)(smc + OFF_ATT);
    float* sS   = (float*)(smc + OFF_SS);
    float* sD   = (float*)(smc + OFF_SD);
    float* sF   = (float*)(smc + OFF_SF);

    // ---- prologue: X [128x128] f32 -> P0 fp16; att vecs; zero scores ----
    {
        const float4* xg4 = (const float4*)(x + (size_t)blockIdx.x * (128 * 128));
        ull_t* A = (ull_t*)(smc + OFF_P0);
#pragma unroll
        for (int t = 0; t < 8; t++) {
            const int idx4 = tid + 512 * t;
            const int row = idx4 >> 5, col4 = idx4 & 31;
            const float4 v = xg4[idx4];
            A[row * 34 + col4] = (ull_t)pk2(v.x, v.y) | ((ull_t)pk2(v.z, v.w) << 32);
        }
    }
    if (tid < 384) {
        sAtt[tid] = (tid < 192) ? __ldg(&as1[tid]) : __ldg(&ad1[tid - 192]);
        sS[tid] = 0.f;
        sD[tid] = 0.f;
    }
    if (tid < 64) sF[tid] = 0.f;
    __syncthreads();

    float dA[4][4];

    // ================= layer 1 =================
    gemm_layer<8>(g_W1h, smc, sbase, tid);
    __syncthreads();
    build_exp_tables(smc, tid);
    __syncthreads();

#pragma unroll
    for (int p = 0; p < 4; p++)
#pragma unroll
        for (int q = 0; q < 4; q++) dA[p][q] = 0.f;
    softmax_agg(dA, smc, sbase, tid);
    __syncthreads();

    // epilogue 1: head-mean + bias + lrelu -> X2 row-major fp16 into P0
    {
        const int m0 = (warp & 7) * 16;
        const int n0 = (warp >> 3) * 32;
        const int g = lane >> 2, tg = lane & 3;
        const int r = m0 + g;
#pragma unroll
        for (int p = 0; p < 4; p++) {
            const int c = n0 + 8 * p + 2 * tg;
            const float bb0 = __ldg(&b1[c]), bb1 = __ldg(&b1[c + 1]);
            float v0 = dA[p][0] * (1.f / 3.f) + bb0;
            float v1 = dA[p][1] * (1.f / 3.f) + bb1;
            float v2 = dA[p][2] * (1.f / 3.f) + bb0;
            float v3 = dA[p][3] * (1.f / 3.f) + bb1;
            v0 = (v0 >= 0.f) ? v0 : 0.01f * v0;
            v1 = (v1 >= 0.f) ? v1 : 0.01f * v1;
            v2 = (v2 >= 0.f) ? v2 : 0.01f * v2;
            v3 = (v3 >= 0.f) ? v3 : 0.01f * v3;
            char* base = smc + OFF_P0 + r * 272 + c * 2;
            *(uint_t*)(base)           = pk2(v0, v1);
            *(uint_t*)(base + 8 * 272) = pk2(v2, v3);
        }
    }
    if (tid < 384) {
        sAtt[tid] = (tid < 192) ? __ldg(&as2[tid]) : __ldg(&ad2[tid - 192]);
        sS[tid] = 0.f;
        sD[tid] = 0.f;
    }
    __syncthreads();

    // ================= layer 2 =================
    gemm_layer<4>(g_W2h, smc, sbase, tid);
    __syncthreads();
    build_exp_tables(smc, tid);
    __syncthreads();

#pragma unroll
    for (int p = 0; p < 4; p++)
#pragma unroll
        for (int q = 0; q < 4; q++) dA[p][q] = 0.f;
    softmax_agg(dA, smc, sbase, tid);

    // epilogue 2: head-mean + bias + lrelu, column-sum over nodes, atomics
    {
        const int n0 = (warp >> 3) * 32;
        const int tg = lane & 3;
#pragma unroll
        for (int p = 0; p < 4; p++) {
            const int c = n0 + 8 * p + 2 * tg;
            const float bb0 = __ldg(&b2[c]), bb1 = __ldg(&b2[c + 1]);
            float v0 = dA[p][0] * (1.f / 3.f) + bb0;
            float v1 = dA[p][1] * (1.f / 3.f) + bb1;
            float v2 = dA[p][2] * (1.f / 3.f) + bb0;
            float v3 = dA[p][3] * (1.f / 3.f) + bb1;
            v0 = (v0 >= 0.f) ? v0 : 0.01f * v0;
            v1 = (v1 >= 0.f) ? v1 : 0.01f * v1;
            v2 = (v2 >= 0.f) ? v2 : 0.01f * v2;
            v3 = (v3 >= 0.f) ? v3 : 0.01f * v3;
            float s0 = v0 + v2;   // column c, two node rows
            float s1 = v1 + v3;   // column c+1
#pragma unroll
            for (int o = 4; o < 32; o <<= 1) {
                s0 += __shfl_xor_sync(0xffffffffu, s0, o);
                s1 += __shfl_xor_sync(0xffffffffu, s1, o);
            }
            if (lane < 4) {
                atomicAdd(&sF[c], s0);
                atomicAdd(&sF[c + 1], s1);
            }
        }
    }
    __syncthreads();
    if (tid < 64) out[(size_t)blockIdx.x * 64 + tid] = sF[tid];
}

// ---------------------------------------------------------------------------
extern "C" void kernel_launch(void* const* d_in, const int* in_sizes, int n_in,
                              void* d_out, int out_size) {
    (void)n_in; (void)out_size;
    const float* x   = (const float*)d_in[0];
    // d_in[1] = batch_mask: equal-sized, sorted graphs -> identity layout
    const float* W1  = (const float*)d_in[2];
    const float* as1 = (const float*)d_in[3];
    const float* ad1 = (const float*)d_in[4];
    const float* b1  = (const float*)d_in[5];
    const float* W2  = (const float*)d_in[6];
    const float* as2 = (const float*)d_in[7];
    const float* ad2 = (const float*)d_in[8];
    const float* b2  = (const float*)d_in[9];
    float* out = (float*)d_out;

    const int B = in_sizes[0] / (128 * 128);

    cvt_weights<<<96, 256>>>(W1, W2);

    cudaFuncSetAttribute(gat_mma_kernel,
                         cudaFuncAttributeMaxDynamicSharedMemorySize, SMEM_BYTES);
    gat_mma_kernel<<<B, 512, SMEM_BYTES>>>(x, as1, ad1, b1,
                                           as2, ad2, b2, out);
}

// round 16
// speedup vs baseline: 1.0127x; 1.0127x over previous
#include <cuda_runtime.h>
#include <cuda_fp16.h>

// ---------------------------------------------------------------------------
// GNNBlock via warp-level mma.sync fp16 (fp32 accumulate), sm_103-safe ISA.
// R14: REGISTER-RESIDENT P. Softmax is computed per-warp directly in the
//      m16n8k16 A-fragment layout (factorized exp tables, no MUFU), scaled
//      with mul.f16x2, and fed straight to the aggregation MMAs: no P smem
//      buffer traffic and zero barriers inside the heads loop.
// GEMM = R9 staged version (fp16 pre-converted W, 2-dbuf, 1 sync/chunk).
// 512 threads/CTA, 2 CTAs/SM. H row-major [node][ch], agg B via ldsm.trans.
// ---------------------------------------------------------------------------

typedef unsigned int uint_t;
typedef unsigned long long ull_t;

// ------------------------- smem byte offsets (per CTA: 109824 B) -----------
#define OFF_P0   0          // X / X2 buffer: 128 rows x 136 fp16 (272 B)
#define OFF_H    34816      // H: 128 rows x 200 fp16 (400 B stride)
#define OFF_BST  86016      // W staging: 2 dbuf x 6400 B
#define OFF_SS   98816      // src scores 3x128 f32
#define OFF_SD   100352     // dst scores 3x128 f32
#define OFF_ES   101888     // exp(S) 3x128 f32
#define OFF_ES2  103424     // exp(0.2 S)
#define OFF_ED   104960     // exp(D)
#define OFF_ED2  106496     // exp(0.2 D)
#define OFF_ATT  108032     // att vecs 2x192 f32
#define OFF_SF   109568     // final pool 64 f32
#define SMEM_BYTES 109824

#define HSTRIDE_B 400       // H / staging row stride bytes
#define STG_DBUF  6400      // staging dbuf stride

// fp16 weight scratch (filled once per launch by cvt_weights)
__device__ __half g_W1h[128 * 192];
__device__ __half g_W2h[64 * 192];

__global__ void cvt_weights(const float* __restrict__ W1,
                            const float* __restrict__ W2) {
    const int i = blockIdx.x * 256 + threadIdx.x;
    if (i < 128 * 192) g_W1h[i] = __float2half(W1[i]);
    if (i < 64 * 192)  g_W2h[i] = __float2half(W2[i]);
}

__device__ __forceinline__ uint_t smem_u32(const void* p) {
    uint_t a;
    asm("{ .reg .u64 t; cvta.to.shared.u64 t, %1; cvt.u32.u64 %0, t; }"
        : "=r"(a) : "l"(p));
    return a;
}
__device__ __forceinline__ void ldsm4(uint_t r[4], uint_t addr) {
    asm volatile("ldmatrix.sync.aligned.m8n8.x4.shared.b16 {%0,%1,%2,%3}, [%4];"
        : "=r"(r[0]), "=r"(r[1]), "=r"(r[2]), "=r"(r[3]) : "r"(addr));
}
__device__ __forceinline__ void ldsm4t(uint_t r[4], uint_t addr) {
    asm volatile("ldmatrix.sync.aligned.m8n8.x4.trans.shared.b16 {%0,%1,%2,%3}, [%4];"
        : "=r"(r[0]), "=r"(r[1]), "=r"(r[2]), "=r"(r[3]) : "r"(addr));
}
__device__ __forceinline__ void mma16816(float d[4], const uint_t a[4],
                                         uint_t b0, uint_t b1) {
    asm volatile("mma.sync.aligned.m16n8k16.row.col.f32.f16.f16.f32 "
        "{%0,%1,%2,%3}, {%4,%5,%6,%7}, {%8,%9}, {%0,%1,%2,%3};"
        : "+f"(d[0]), "+f"(d[1]), "+f"(d[2]), "+f"(d[3])
        : "r"(a[0]), "r"(a[1]), "r"(a[2]), "r"(a[3]), "r"(b0), "r"(b1));
}
// pack (lo, hi) in memory order as fp16x2
__device__ __forceinline__ uint_t pk2(float lo, float hi) {
    uint_t r;
    asm("cvt.rn.f16x2.f32 %0, %1, %2;" : "=r"(r) : "f"(hi), "f"(lo));
    return r;
}
__device__ __forceinline__ uint_t hmul2(uint_t a, uint_t b) {
    uint_t r;
    asm("mul.rn.f16x2 %0, %1, %2;" : "=r"(r) : "r"(a), "r"(b));
    return r;
}

// ---------------------------------------------------------------------------
// GEMM: H (row-major fp16) <- A[128 x 16*NCH] @ W[16*NCH x 192] (W fp16),
// fused per-node attention score partials via smem atomics.
// 16 warps: m0=(w&7)*16, n0=(w>>3)*96 -> 12 m16n8 tiles per warp.
// W staged [k][192] fp16 (2 dbuf, 1 sync/chunk), B fragments via ldsm.trans.
// ---------------------------------------------------------------------------
template <int NCH>
__device__ __forceinline__ void gemm_layer(const __half* __restrict__ Wg,
                                           char* smc, uint_t sbase, int tid) {
    const int warp = tid >> 5, lane = tid & 31;
    const int m0 = (warp & 7) * 16;
    const int n0 = (warp >> 3) * 96;

    float d[12][4];
#pragma unroll
    for (int p = 0; p < 12; p++)
#pragma unroll
        for (int q = 0; q < 4; q++) d[p][q] = 0.f;

    const uint_t aA = sbase + OFF_P0 + (m0 + (lane & 15)) * 272 + ((lane >> 4) << 4);
    const uint_t bOff = (lane & 15) * HSTRIDE_B + ((n0 + ((lane >> 4) << 3)) << 1);

    // staging producers: 768 x 8B per chunk; thread does idx=tid and
    // (tid<256) idx=tid+512.  sk=idx/48 (k row), sc=(idx%48)*4 (col).
    const int sk0 = tid / 48,         sc0 = (tid % 48) * 4;
    const int sk1 = (tid + 512) / 48, sc1 = ((tid + 512) % 48) * 4;
    ull_t pre0 = *(const ull_t*)(Wg + sk0 * 192 + sc0);
    ull_t pre1 = 0;
    if (tid < 256) pre1 = *(const ull_t*)(Wg + sk1 * 192 + sc1);

    for (int ch = 0; ch < NCH; ch++) {
        {
            char* stg = smc + OFF_BST + (ch & 1) * STG_DBUF;
            *(ull_t*)(stg + sk0 * HSTRIDE_B + sc0 * 2) = pre0;
            if (tid < 256)
                *(ull_t*)(stg + sk1 * HSTRIDE_B + sc1 * 2) = pre1;
        }
        __syncthreads();
        if (ch + 1 < NCH) {
            const __half* w = Wg + (ch + 1) * 16 * 192;
            pre0 = *(const ull_t*)(w + sk0 * 192 + sc0);
            if (tid < 256) pre1 = *(const ull_t*)(w + sk1 * 192 + sc1);
        }
        uint_t a[4];
        ldsm4(a, aA + ch * 32);
        const uint_t bB = sbase + OFF_BST + (ch & 1) * STG_DBUF + bOff;
#pragma unroll
        for (int pp = 0; pp < 6; pp++) {
            uint_t b[4];
            ldsm4t(b, bB + pp * 32);
            mma16816(d[2 * pp],     a, b[0], b[1]);
            mma16816(d[2 * pp + 1], a, b[2], b[3]);
        }
    }

    // ---- epilogue: H row-major STS.32 + fused score partials ----
    const int g = lane >> 2, tg = lane & 3;
    const float* sAtt = (const float*)(smc + OFF_ATT);
    float* sS = (float*)(smc + OFF_SS);
    float* sD = (float*)(smc + OFF_SD);
    const int first = n0 >> 6;        // 0 or 1; 96-col span covers 2 head slots
    const int r = m0 + g;

    float ps[2][2] = {{0.f, 0.f}, {0.f, 0.f}};
    float pd[2][2] = {{0.f, 0.f}, {0.f, 0.f}};
#pragma unroll
    for (int p = 0; p < 12; p++) {
        const int c = n0 + 8 * p + 2 * tg;
        const int slot = ((n0 + 8 * p) >> 6) - first;   // 0 or 1
        const float as0 = sAtt[c],       as1 = sAtt[c + 1];
        const float ad0 = sAtt[192 + c], ad1 = sAtt[192 + c + 1];
        const float q0 = d[p][0], q1 = d[p][1], q2 = d[p][2], q3 = d[p][3];
        char* base = smc + OFF_H + r * HSTRIDE_B + c * 2;
        *(uint_t*)(base)                 = pk2(q0, q1);
        *(uint_t*)(base + 8 * HSTRIDE_B) = pk2(q2, q3);
        ps[0][slot] += q0 * as0 + q1 * as1;
        pd[0][slot] += q0 * ad0 + q1 * ad1;
        ps[1][slot] += q2 * as0 + q3 * as1;
        pd[1][slot] += q2 * ad0 + q3 * ad1;
    }
#pragma unroll
    for (int rh = 0; rh < 2; rh++)
#pragma unroll
        for (int sl = 0; sl < 2; sl++) {
            float a = ps[rh][sl], b = pd[rh][sl];
            a += __shfl_xor_sync(0xffffffffu, a, 1);
            a += __shfl_xor_sync(0xffffffffu, a, 2);
            b += __shfl_xor_sync(0xffffffffu, b, 1);
            b += __shfl_xor_sync(0xffffffffu, b, 2);
            ps[rh][sl] = a; pd[rh][sl] = b;
        }
    if (tg == 0) {
#pragma unroll
        for (int rh = 0; rh < 2; rh++) {
            const int row = r + 8 * rh;
            atomicAdd(&sS[first * 128 + row],       ps[rh][0]);
            atomicAdd(&sD[first * 128 + row],       pd[rh][0]);
            atomicAdd(&sS[(first + 1) * 128 + row], ps[rh][1]);
            atomicAdd(&sD[(first + 1) * 128 + row], pd[rh][1]);
        }
    }
}

// ---------------------------------------------------------------------------
// Exp tables: thread t<384 handles (n, h): Es=e^S, Es2=e^{0.2S}, Ed, Ed2.
// The only MUFU work in the whole attention phase.
// ---------------------------------------------------------------------------
__device__ __forceinline__ void build_exp_tables(char* smc, int tid) {
    if (tid < 384) {
        const float s = ((const float*)(smc + OFF_SS))[tid];
        const float d = ((const float*)(smc + OFF_SD))[tid];
        ((float*)(smc + OFF_ES))[tid]  = __expf(s);
        ((float*)(smc + OFF_ES2))[tid] = __expf(0.2f * s);
        ((float*)(smc + OFF_ED))[tid]  = __expf(d);
        ((float*)(smc + OFF_ED2))[tid] = __expf(0.2f * d);
    }
}

// ---------------------------------------------------------------------------
// Fused softmax + aggregation, P register-resident in A-fragment layout.
// Warp w: m0=(w&7)*16 rows, n0=(w>>3)*32 cols of the output; for each head:
//   - compute its 16 rows' softmax weights directly as fragments
//     (thread owns rows {q, q+8}, cols {2t,2t+1,2t+8,2t+9} per 16-chunk)
//   - 2-shfl row-sum over the 4 lanes sharing a row, scale via mul.f16x2
//   - 32 MMAs against H_h (ldsm.trans B).  NO barriers, NO P smem traffic.
// ---------------------------------------------------------------------------
__device__ __forceinline__ void softmax_agg(float dA[4][4], char* smc,
                                            uint_t sbase, int tid) {
    const int warp = tid >> 5, lane = tid & 31;
    const int m0 = (warp & 7) * 16;
    const int n0 = (warp >> 3) * 32;
    const int q = lane >> 2, t = lane & 3;
    const int r0 = m0 + q, r1 = r0 + 8;
    const uint_t bBase = sbase + OFF_H + (lane & 15) * HSTRIDE_B
                       + ((n0 + ((lane >> 4) << 3)) << 1);

#pragma unroll 1
    for (int h = 0; h < 3; h++) {
        const float* Ss  = (const float*)(smc + OFF_SS)  + h * 128;
        const float* Es  = (const float*)(smc + OFF_ES)  + h * 128;
        const float* Es2 = (const float*)(smc + OFF_ES2) + h * 128;
        const float* Sd  = (const float*)(smc + OFF_SD)  + h * 128;
        const float* Ed  = (const float*)(smc + OFF_ED)  + h * 128;
        const float* Ed2 = (const float*)(smc + OFF_ED2) + h * 128;
        const float d0 = Sd[r0], d1 = Sd[r1];
        const float ed0 = Ed[r0], eb0 = Ed2[r0];
        const float ed1 = Ed[r1], eb1 = Ed2[r1];

        uint_t fr[8][4];
        float sum0 = 0.f, sum1 = 0.f;
#pragma unroll
        for (int ch = 0; ch < 8; ch++) {
            const int j0 = ch * 16 + 2 * t;
            const float2 sA = *(const float2*)(Ss + j0);
            const float2 sB = *(const float2*)(Ss + j0 + 8);
            const float2 eA = *(const float2*)(Es + j0);
            const float2 eB = *(const float2*)(Es + j0 + 8);
            const float2 qA = *(const float2*)(Es2 + j0);
            const float2 qB = *(const float2*)(Es2 + j0 + 8);
            const float e00 = (sA.x + d0 >= 0.f) ? eA.x * ed0 : qA.x * eb0;
            const float e01 = (sA.y + d0 >= 0.f) ? eA.y * ed0 : qA.y * eb0;
            const float e02 = (sB.x + d0 >= 0.f) ? eB.x * ed0 : qB.x * eb0;
            const float e03 = (sB.y + d0 >= 0.f) ? eB.y * ed0 : qB.y * eb0;
            const float e10 = (sA.x + d1 >= 0.f) ? eA.x * ed1 : qA.x * eb1;
            const float e11 = (sA.y + d1 >= 0.f) ? eA.y * ed1 : qA.y * eb1;
            const float e12 = (sB.x + d1 >= 0.f) ? eB.x * ed1 : qB.x * eb1;
            const float e13 = (sB.y + d1 >= 0.f) ? eB.y * ed1 : qB.y * eb1;
            sum0 += (e00 + e01) + (e02 + e03);
            sum1 += (e10 + e11) + (e12 + e13);
            fr[ch][0] = pk2(e00, e01);
            fr[ch][1] = pk2(e10, e11);
            fr[ch][2] = pk2(e02, e03);
            fr[ch][3] = pk2(e12, e13);
        }
        // row sums: 4 lanes (4q..4q+3) share each row
        sum0 += __shfl_xor_sync(0xffffffffu, sum0, 1);
        sum0 += __shfl_xor_sync(0xffffffffu, sum0, 2);
        sum1 += __shfl_xor_sync(0xffffffffu, sum1, 1);
        sum1 += __shfl_xor_sync(0xffffffffu, sum1, 2);
        const float i0 = __fdividef(1.f, sum0);
        const float i1 = __fdividef(1.f, sum1);
        const uint_t iv0 = pk2(i0, i0), iv1 = pk2(i1, i1);
#pragma unroll
        for (int ch = 0; ch < 8; ch++) {
            fr[ch][0] = hmul2(fr[ch][0], iv0);
            fr[ch][1] = hmul2(fr[ch][1], iv1);
            fr[ch][2] = hmul2(fr[ch][2], iv0);
            fr[ch][3] = hmul2(fr[ch][3], iv1);
        }
        // aggregate: dA += P_frag @ H_h
        const uint_t bB = bBase + (h << 7);     // +64h fp16 cols
#pragma unroll
        for (int s = 0; s < 8; s++) {
#pragma unroll
            for (int pp = 0; pp < 2; pp++) {
                uint_t b[4];
                ldsm4t(b, bB + s * (16 * HSTRIDE_B) + pp * 32);
                mma16816(dA[2 * pp],     fr[s], b[0], b[1]);
                mma16816(dA[2 * pp + 1], fr[s], b[2], b[3]);
            }
        }
    }
}

// ---------------------------------------------------------------------------
__global__ void __launch_bounds__(512, 2)
gat_mma_kernel(const float* __restrict__ x,
               const float* __restrict__ as1, const float* __restrict__ ad1,
               const float* __restrict__ b1,
               const float* __restrict__ as2, const float* __restrict__ ad2,
               const float* __restrict__ b2,
               float* __restrict__ out) {
    extern __shared__ char smc[];
    const uint_t sbase = smem_u32(smc);
    const int tid = threadIdx.x;
    const int warp = tid >> 5, lane = tid & 31;

    float* sAtt = (float*)(smc + OFF_ATT);
    float* sS   = (float*)(smc + OFF_SS);
    float* sD   = (float*)(smc + OFF_SD);
    float* sF   = (float*)(smc + OFF_SF);

    // ---- prologue: X [128x128] f32 -> P0 fp16; att vecs; zero scores ----
    {
        const float4* xg4 = (const float4*)(x + (size_t)blockIdx.x * (128 * 128));
        ull_t* A = (ull_t*)(smc + OFF_P0);
#pragma unroll
        for (int t = 0; t < 8; t++) {
            const int idx4 = tid + 512 * t;
            const int row = idx4 >> 5, col4 = idx4 & 31;
            const float4 v = xg4[idx4];
            A[row * 34 + col4] = (ull_t)pk2(v.x, v.y) | ((ull_t)pk2(v.z, v.w) << 32);
        }
    }
    if (tid < 384) {
        sAtt[tid] = (tid < 192) ? __ldg(&as1[tid]) : __ldg(&ad1[tid - 192]);
        sS[tid] = 0.f;
        sD[tid] = 0.f;
    }
    if (tid < 64) sF[tid] = 0.f;
    __syncthreads();

    float dA[4][4];

    // ================= layer 1 =================
    gemm_layer<8>(g_W1h, smc, sbase, tid);
    __syncthreads();
    build_exp_tables(smc, tid);
    __syncthreads();

#pragma unroll
    for (int p = 0; p < 4; p++)
#pragma unroll
        for (int q = 0; q < 4; q++) dA[p][q] = 0.f;
    softmax_agg(dA, smc, sbase, tid);
    __syncthreads();

    // epilogue 1: head-mean + bias + lrelu -> X2 row-major fp16 into P0
    {
        const int m0 = (warp & 7) * 16;
        const int n0 = (warp >> 3) * 32;
        const int g = lane >> 2, tg = lane & 3;
        const int r = m0 + g;
#pragma unroll
        for (int p = 0; p < 4; p++) {
            const int c = n0 + 8 * p + 2 * tg;
            const float bb0 = __ldg(&b1[c]), bb1 = __ldg(&b1[c + 1]);
            float v0 = dA[p][0] * (1.f / 3.f) + bb0;
            float v1 = dA[p][1] * (1.f / 3.f) + bb1;
            float v2 = dA[p][2] * (1.f / 3.f) + bb0;
            float v3 = dA[p][3] * (1.f / 3.f) + bb1;
            v0 = (v0 >= 0.f) ? v0 : 0.01f * v0;
            v1 = (v1 >= 0.f) ? v1 : 0.01f * v1;
            v2 = (v2 >= 0.f) ? v2 : 0.01f * v2;
            v3 = (v3 >= 0.f) ? v3 : 0.01f * v3;
            char* base = smc + OFF_P0 + r * 272 + c * 2;
            *(uint_t*)(base)           = pk2(v0, v1);
            *(uint_t*)(base + 8 * 272) = pk2(v2, v3);
        }
    }
    if (tid < 384) {
        sAtt[tid] = (tid < 192) ? __ldg(&as2[tid]) : __ldg(&ad2[tid - 192]);
        sS[tid] = 0.f;
        sD[tid] = 0.f;
    }
    __syncthreads();

    // ================= layer 2 =================
    gemm_layer<4>(g_W2h, smc, sbase, tid);
    __syncthreads();
    build_exp_tables(smc, tid);
    __syncthreads();

#pragma unroll
    for (int p = 0; p < 4; p++)
#pragma unroll
        for (int q = 0; q < 4; q++) dA[p][q] = 0.f;
    softmax_agg(dA, smc, sbase, tid);

    // epilogue 2: head-mean + bias + lrelu, column-sum over nodes, atomics
    {
        const int n0 = (warp >> 3) * 32;
        const int tg = lane & 3;
#pragma unroll
        for (int p = 0; p < 4; p++) {
            const int c = n0 + 8 * p + 2 * tg;
            const float bb0 = __ldg(&b2[c]), bb1 = __ldg(&b2[c + 1]);
            float v0 = dA[p][0] * (1.f / 3.f) + bb0;
            float v1 = dA[p][1] * (1.f / 3.f) + bb1;
            float v2 = dA[p][2] * (1.f / 3.f) + bb0;
            float v3 = dA[p][3] * (1.f / 3.f) + bb1;
            v0 = (v0 >= 0.f) ? v0 : 0.01f * v0;
            v1 = (v1 >= 0.f) ? v1 : 0.01f * v1;
            v2 = (v2 >= 0.f) ? v2 : 0.01f * v2;
            v3 = (v3 >= 0.f) ? v3 : 0.01f * v3;
            float s0 = v0 + v2;   // column c, two node rows
            float s1 = v1 + v3;   // column c+1
#pragma unroll
            for (int o = 4; o < 32; o <<= 1) {
                s0 += __shfl_xor_sync(0xffffffffu, s0, o);
                s1 += __shfl_xor_sync(0xffffffffu, s1, o);
            }
            if (lane < 4) {
                atomicAdd(&sF[c], s0);
                atomicAdd(&sF[c + 1], s1);
            }
        }
    }
    __syncthreads();
    if (tid < 64) out[(size_t)blockIdx.x * 64 + tid] = sF[tid];
}

// ---------------------------------------------------------------------------
extern "C" void kernel_launch(void* const* d_in, const int* in_sizes, int n_in,
                              void* d_out, int out_size) {
    (void)n_in; (void)out_size;
    const float* x   = (const float*)d_in[0];
    // d_in[1] = batch_mask: equal-sized, sorted graphs -> identity layout
    const float* W1  = (const float*)d_in[2];
    const float* as1 = (const float*)d_in[3];
    const float* ad1 = (const float*)d_in[4];
    const float* b1  = (const float*)d_in[5];
    const float* W2  = (const float*)d_in[6];
    const float* as2 = (const float*)d_in[7];
    const float* ad2 = (const float*)d_in[8];
    const float* b2  = (const float*)d_in[9];
    float* out = (float*)d_out;

    const int B = in_sizes[0] / (128 * 128);

    cvt_weights<<<96, 256>>>(W1, W2);

    cudaFuncSetAttribute(gat_mma_kernel,
                         cudaFuncAttributeMaxDynamicSharedMemorySize, SMEM_BYTES);
    gat_mma_kernel<<<B, 512, SMEM_BYTES>>>(x, as1, ad1, b1,
                                           as2, ad2, b2, out);
}